// round 10
// baseline (speedup 1.0000x reference)
#include <cuda_runtime.h>
#include <cuda_bf16.h>
#include <cstdint>

#define IN_F   4096
#define OUT_F  4096
#define NTOK   16384
#define BW     8
#define KW     17          // 2*BW+1
#define NO     4           // outputs per thread
#define WARPS  8           // warps per block (256 threads)
#define GY     256         // token stride / grid.y  -> 64 tokens per block
#define WIN4   36          // float4 chunks per warp window (144 floats)
#define SBUF4  40          // chunks per token buffer
#define NPAIR  8           // pair slots per warp
#define NBUF   (2*NPAIR)   // 16 token buffers
#define NITER  16          // 32 pairs, 2 pairs per iteration
#define BROWS  (WARPS * 32 * NO)           // 1024 band rows per block
#define WST_F  (BROWS * KW)                // 17408 staged weight floats
#define PIPE_B (WARPS * NBUF * SBUF4 * 16) // 81920 B
#define WST_B  (WST_F * 4)                 // 69632 B
#define SMEM_B (WST_B > PIPE_B ? WST_B : PIPE_B)   // 81920 B

__device__ __forceinline__ void cp16(uint32_t dst_smem, const float* src) {
    asm volatile("cp.async.cg.shared.global [%0], [%1], 16;\n"
                 :: "r"(dst_smem), "l"(src) : "memory");
}
__device__ __forceinline__ void cp4(uint32_t dst_smem, const float* src) {
    asm volatile("cp.async.ca.shared.global [%0], [%1], 4;\n"
                 :: "r"(dst_smem), "l"(src) : "memory");
}
__device__ __forceinline__ void cp_commit() {
    asm volatile("cp.async.commit_group;\n" ::: "memory");
}

// ---- packed f32x2 helpers (sm_103a) ----
__device__ __forceinline__ uint64_t pk2(float lo, float hi) {
    uint64_t r;
    asm("mov.b64 %0, {%1, %2};" : "=l"(r) : "f"(lo), "f"(hi));
    return r;
}
__device__ __forceinline__ void fma2(uint64_t& d, uint64_t a, uint64_t b) {
    asm("fma.rn.f32x2 %0, %1, %2, %0;" : "+l"(d) : "l"(a), "l"(b));
}
__device__ __forceinline__ void upk2(float& lo, float& hi, uint64_t v) {
    asm("mov.b64 {%0, %1}, %2;" : "=f"(lo), "=f"(hi) : "l"(v));
}

// warp covers 32*NO = 128 consecutive outputs; block covers 1024; grid.x = 4.
__global__ __launch_bounds__(256, 1) void band_linear_kernel(
    const float* __restrict__ x,
    const float* __restrict__ w,
    const float* __restrict__ bias,
    float* __restrict__ out)
{
    extern __shared__ char dsm[];
    float4* smp = reinterpret_cast<float4*>(dsm);         // x pipeline (after weights consumed)
    float*  smw = reinterpret_cast<float*>(dsm);          // weight stage (union)

    const int warp = threadIdx.x >> 5;
    const int lane = threadIdx.x & 31;
    const int wbase  = (blockIdx.x * WARPS + warp) * (32 * NO);
    const int o_base = wbase + lane * NO;
    const int win0   = wbase - BW;               // multiple of 4

    // ---- async coalesced weight staging: 1024 rows x 17 taps, one group ----
    {
        const int row0 = blockIdx.x * BROWS;
        const uint32_t smw_a = (uint32_t)__cvta_generic_to_shared(smw);
#pragma unroll
        for (int i = 0; i < WST_F / 256; ++i) {              // 68 cp.async each
            const int e = threadIdx.x + i * 256;
            const int r = e / KW;
            const int k = e - r * KW;
            const int o = row0 + r;
            int col = o - BW + k;
            col = col < 0 ? 0 : (col >= IN_F ? IN_F - 1 : col);  // clamp; zeroed later
            cp4(smw_a + (uint32_t)(e * 4), w + (long)o * IN_F + col);
        }
        cp_commit();
    }
    asm volatile("cp.async.wait_group 0;\n" ::: "memory");
    __syncthreads();

    // ---- copy weights smem -> PACKED registers {w,w}; smem recycled after ----
    uint64_t wp[NO][KW];
    uint64_t bp[NO];
    {
        const int rloc = warp * 128 + lane * NO;
#pragma unroll
        for (int oo = 0; oo < NO; ++oo) {
            const int o = o_base + oo;
            const float b = bias[o];
            bp[oo] = pk2(b, b);
#pragma unroll
            for (int k = 0; k < KW; ++k) {
                const int col = o - BW + k;
                float v = smw[(rloc + oo) * KW + k];
                v = (col >= 0 && col < IN_F) ? v : 0.0f;
                wp[oo][k] = pk2(v, v);
            }
        }
    }
    __syncthreads();   // all reads of smw done before pipeline overwrites it

    // ---- x staging chunk assignment (coalesced, 36 chunks over 32 lanes) ----
    const int  c0    = lane;
    const bool extra = (lane < WIN4 - 32);   // lanes 0..3 take chunks 32..35
    const int  c1    = 32 + lane;

    int s0 = win0 + 4 * c0;
    s0 = s0 < 0 ? 0 : (s0 > IN_F - 4 ? IN_F - 4 : s0);
    int s1 = win0 + 4 * c1;
    s1 = s1 < 0 ? 0 : (s1 > IN_F - 4 ? IN_F - 4 : s1);
    // clamped chunks pair only with zero weights -> harmless.

    const uint32_t wsm  = (uint32_t)__cvta_generic_to_shared(smp + (size_t)warp * NBUF * SBUF4);
    const uint32_t off0 = (uint32_t)(c0 * 16);
    const uint32_t off1 = (uint32_t)(c1 * 16);

    const int n0 = blockIdx.y;

    // stage one token into token-buffer bi
    auto stage_tok = [&](int tok, int bi) {
        const float* xrow = x + (long)tok * IN_F;
        const uint32_t b = wsm + (uint32_t)(bi * SBUF4 * 16);
        cp16(b + off0, xrow + s0);
        if (extra) cp16(b + off1, xrow + s1);
    };

    // ---- prologue: stage pairs 0..3 into slots 0..3 (one group per pair) ----
#pragma unroll
    for (int p = 0; p < 4; ++p) {
        stage_tok(n0 + (2 * p) * GY,     2 * p);
        stage_tok(n0 + (2 * p + 1) * GY, 2 * p + 1);
        cp_commit();
    }

    int cs = 0;   // slot holding current pair
    int ps = 4;   // slot to fill next
    for (int it = 0; it < NITER; ++it) {
        // ---- prefetch pairs 2*it+4, 2*it+5 (guarded), one group each ----
#pragma unroll
        for (int j = 0; j < 2; ++j) {
            const int pp = 2 * it + 4 + j;
            if (pp < 32) {
                const int sl = (ps + j) & (NPAIR - 1);
                stage_tok(n0 + (2 * pp) * GY,     2 * sl);
                stage_tok(n0 + (2 * pp + 1) * GY, 2 * sl + 1);
            }
            cp_commit();
        }

        // ---- wait: <=4 pending => slots cs, cs+1 complete ----
        asm volatile("cp.async.wait_group 4;\n" ::: "memory");
        __syncwarp();

        const float* pb = reinterpret_cast<const float*>(smp + (size_t)warp * NBUF * SBUF4);

        // ---- process 2 pairs (4 tokens) ----
#pragma unroll
        for (int j = 0; j < 2; ++j) {
            const int p  = 2 * it + j;                 // pair index 0..31
            const int sl = (cs + j) & (NPAIR - 1);
            const int tA = n0 + (2 * p) * GY;
            const float* bA = pb + (size_t)(2 * sl)     * SBUF4 * 4;
            const float* bB = pb + (size_t)(2 * sl + 1) * SBUF4 * 4;

            // load both windows, pack {A,B}
            uint64_t xp[NO + 2 * BW];   // 20 packed
#pragma unroll
            for (int c = 0; c < 5; ++c) {
                const float4 a4 = *reinterpret_cast<const float4*>(bA + lane * NO + 4 * c);
                const float4 b4 = *reinterpret_cast<const float4*>(bB + lane * NO + 4 * c);
                xp[4 * c + 0] = pk2(a4.x, b4.x);
                xp[4 * c + 1] = pk2(a4.y, b4.y);
                xp[4 * c + 2] = pk2(a4.z, b4.z);
                xp[4 * c + 3] = pk2(a4.w, b4.w);
            }

            uint64_t acc[NO];
#pragma unroll
            for (int oo = 0; oo < NO; ++oo) {
                acc[oo] = bp[oo];
#pragma unroll
                for (int k = 0; k < KW; ++k)
                    fma2(acc[oo], xp[oo + k], wp[oo][k]);
            }

            float4 oA, oB;
            upk2(oA.x, oB.x, acc[0]);
            upk2(oA.y, oB.y, acc[1]);
            upk2(oA.z, oB.z, acc[2]);
            upk2(oA.w, oB.w, acc[3]);
            *reinterpret_cast<float4*>(out + (long)tA * OUT_F + o_base)        = oA;
            *reinterpret_cast<float4*>(out + (long)(tA + GY) * OUT_F + o_base) = oB;
        }

        cs = (cs + 2) & (NPAIR - 1);
        ps = (ps + 2) & (NPAIR - 1);
    }
}

extern "C" void kernel_launch(void* const* d_in, const int* in_sizes, int n_in,
                              void* d_out, int out_size)
{
    const float* x    = (const float*)d_in[0];   // [NTOK, IN_F]
    const float* w    = (const float*)d_in[1];   // [OUT_F, IN_F]
    const float* bias = (const float*)d_in[2];   // [OUT_F]
    float* out = (float*)d_out;

    cudaFuncSetAttribute(band_linear_kernel,
                         cudaFuncAttributeMaxDynamicSharedMemorySize, SMEM_B);

    dim3 grid(OUT_F / (WARPS * 32 * NO), GY);    // (4, 256)
    dim3 block(WARPS * 32);                      // 256
    band_linear_kernel<<<grid, block, SMEM_B>>>(x, w, bias, out);
}

// round 11
// speedup vs baseline: 1.2332x; 1.2332x over previous
#include <cuda_runtime.h>
#include <cuda_bf16.h>
#include <cstdint>

#define IN_F   4096
#define OUT_F  4096
#define NTOK   16384
#define BW     8
#define KW     17          // 2*BW+1
#define NO     4           // outputs per thread
#define NP     9           // packed weight pairs per output
#define WARPS  8           // warps per block (256 threads)
#define GY     256         // token stride / grid.y  -> 64 tokens per block
#define WIN4   36          // float4 chunks per warp window (144 floats)
#define SBUF4  40          // chunks per buffer
#define NBUF   8
#define PDIST  6
#define BROWS  (WARPS * 32 * NO)           // 1024 band rows per block
#define WST_F  (BROWS * KW)                // 17408 staged weight floats
#define PIPE_B (WARPS * NBUF * SBUF4 * 16) // 40960 B
#define WST_B  (WST_F * 4)                 // 69632 B
#define SMEM_B (WST_B > PIPE_B ? WST_B : PIPE_B)   // 69632 B

__device__ __forceinline__ void cp16(uint32_t dst_smem, const float* src) {
    asm volatile("cp.async.cg.shared.global [%0], [%1], 16;\n"
                 :: "r"(dst_smem), "l"(src) : "memory");
}
__device__ __forceinline__ void cp4(uint32_t dst_smem, const float* src) {
    asm volatile("cp.async.ca.shared.global [%0], [%1], 4;\n"
                 :: "r"(dst_smem), "l"(src) : "memory");
}
__device__ __forceinline__ void cp_commit() {
    asm volatile("cp.async.commit_group;\n" ::: "memory");
}

// ---- packed f32x2 helpers (sm_103a) ----
__device__ __forceinline__ uint64_t pk2(float lo, float hi) {
    uint64_t r;
    asm("mov.b64 %0, {%1, %2};" : "=l"(r) : "f"(lo), "f"(hi));
    return r;
}
// d += {alo,ahi} * b   (lanes independent); alo/ahi come from aligned LDS quads
__device__ __forceinline__ void fma2f(uint64_t& d, float alo, float ahi, uint64_t b) {
    asm("{\n\t.reg .b64 t;\n\tmov.b64 t, {%1, %2};\n\t"
        "fma.rn.f32x2 %0, t, %3, %0;\n\t}"
        : "+l"(d) : "f"(alo), "f"(ahi), "l"(b));
}
__device__ __forceinline__ void upk2(float& lo, float& hi, uint64_t v) {
    asm("mov.b64 {%0, %1}, %2;" : "=f"(lo), "=f"(hi) : "l"(v));
}

// warp covers 32*NO = 128 consecutive outputs; block covers 1024; grid.x = 4.
__global__ __launch_bounds__(256, 2) void band_linear_kernel(
    const float* __restrict__ x,
    const float* __restrict__ w,
    const float* __restrict__ bias,
    float* __restrict__ out)
{
    extern __shared__ char dsm[];
    float4* smp = reinterpret_cast<float4*>(dsm);         // x pipeline (after weights consumed)
    float*  smw = reinterpret_cast<float*>(dsm);          // weight stage (union)

    const int warp = threadIdx.x >> 5;
    const int lane = threadIdx.x & 31;
    const int wbase  = (blockIdx.x * WARPS + warp) * (32 * NO);
    const int o_base = wbase + lane * NO;
    const int win0   = wbase - BW;               // multiple of 4

    // ---- async coalesced weight staging: 1024 rows x 17 taps, one group ----
    {
        const int row0 = blockIdx.x * BROWS;
        const uint32_t smw_a = (uint32_t)__cvta_generic_to_shared(smw);
#pragma unroll
        for (int i = 0; i < WST_F / 256; ++i) {              // 68 cp.async each
            const int e = threadIdx.x + i * 256;
            const int r = e / KW;
            const int k = e - r * KW;
            const int o = row0 + r;
            int col = o - BW + k;
            col = col < 0 ? 0 : (col >= IN_F ? IN_F - 1 : col);  // clamp; zeroed later
            cp4(smw_a + (uint32_t)(e * 4), w + (long)o * IN_F + col);
        }
        cp_commit();
    }
    asm volatile("cp.async.wait_group 0;\n" ::: "memory");
    __syncthreads();

    // ---- build PACKED tap-pair weights in registers; smem recycled after ----
    // Output oo (o = o_base+oo) consumes window elems j in [oo, oo+16].
    // Even-aligned pairs m: {xr[2m], xr[2m+1]}, absolute m = (oo>>1) .. (oo>>1)+8.
    // Packed weight for (oo, m): {w_o[2m-oo], w_o[2m+1-oo]}, zero-padded outside [0,17).
    uint64_t wpk[NO][NP];
    uint64_t bp[NO];
    {
        const int rloc = warp * 128 + lane * NO;
#pragma unroll
        for (int oo = 0; oo < NO; ++oo) {
            const int o = o_base + oo;
            bp[oo] = pk2(bias[o], 0.0f);
            const int ms = oo >> 1;
#pragma unroll
            for (int m = 0; m < NP; ++m) {
                const int am  = ms + m;          // absolute pair index
                const int klo = 2 * am - oo;     // weight tap for lo lane
                const int khi = klo + 1;
                float vlo = 0.0f, vhi = 0.0f;
                if (klo >= 0 && klo < KW) {
                    const int col = o - BW + klo;
                    const float v = smw[(rloc + oo) * KW + klo];
                    vlo = (col >= 0 && col < IN_F) ? v : 0.0f;
                }
                if (khi >= 0 && khi < KW) {
                    const int col = o - BW + khi;
                    const float v = smw[(rloc + oo) * KW + khi];
                    vhi = (col >= 0 && col < IN_F) ? v : 0.0f;
                }
                wpk[oo][m] = pk2(vlo, vhi);
            }
        }
    }
    __syncthreads();   // all reads of smw done before pipeline overwrites it

    // ---- x staging chunk assignment (coalesced, 36 chunks over 32 lanes) ----
    const int  c0    = lane;
    const bool extra = (lane < WIN4 - 32);   // lanes 0..3 take chunks 32..35
    const int  c1    = 32 + lane;

    int s0 = win0 + 4 * c0;
    s0 = s0 < 0 ? 0 : (s0 > IN_F - 4 ? IN_F - 4 : s0);
    int s1 = win0 + 4 * c1;
    s1 = s1 < 0 ? 0 : (s1 > IN_F - 4 ? IN_F - 4 : s1);
    // clamped chunks pair only with zero weights -> harmless.

    const uint32_t wsm  = (uint32_t)__cvta_generic_to_shared(smp + (size_t)warp * NBUF * SBUF4);
    const uint32_t off0 = (uint32_t)(c0 * 16);
    const uint32_t off1 = (uint32_t)(c1 * 16);

    const int n0 = blockIdx.y;

    // ---- prologue: stage tokens n0 .. n0+5*GY into buffers 0..5 ----
#pragma unroll
    for (int p = 0; p < PDIST; ++p) {
        const int tn = n0 + p * GY;        // always < NTOK
        const float* xrow = x + (long)tn * IN_F;
        const uint32_t b = wsm + (uint32_t)(p * SBUF4 * 16);
        cp16(b + off0, xrow + s0);
        if (extra) cp16(b + off1, xrow + s1);
        cp_commit();
    }

    int buf  = 0;
    int pbuf = PDIST;
    for (int n = n0; n < NTOK; n += 2 * GY) {
        // ---- stage tokens n+6*GY and n+7*GY (two groups) ----
        {
            const int pnA = n + PDIST * GY;
            if (pnA < NTOK) {
                const float* xrow = x + (long)pnA * IN_F;
                const uint32_t b = wsm + (uint32_t)(pbuf * SBUF4 * 16);
                cp16(b + off0, xrow + s0);
                if (extra) cp16(b + off1, xrow + s1);
            }
            cp_commit();
            const int pnB = n + (PDIST + 1) * GY;
            if (pnB < NTOK) {
                const float* xrow = x + (long)pnB * IN_F;
                const uint32_t b = wsm + (uint32_t)(((pbuf + 1) & (NBUF - 1)) * SBUF4 * 16);
                cp16(b + off0, xrow + s0);
                if (extra) cp16(b + off1, xrow + s1);
            }
            cp_commit();
        }

        // ---- wait: <= PDIST groups pending => bufs (buf, buf+1) complete ----
        asm volatile("cp.async.wait_group %0;\n" :: "n"(PDIST) : "memory");
        __syncwarp();

        const float* wb = reinterpret_cast<const float*>(smp + (size_t)warp * NBUF * SBUF4);

#pragma unroll
        for (int t = 0; t < 2; ++t) {
            const int nt = n + t * GY;     // always < NTOK (n0 < GY)
            const float* swp = wb + (size_t)((buf + t) & (NBUF - 1)) * SBUF4 * 4;

            // window: 5 conflict-free LDS.128 -> 10 aligned float2 pairs
            float xr[NO + 2 * BW];  // 20
#pragma unroll
            for (int c = 0; c < 5; ++c) {
                const float4 v = *reinterpret_cast<const float4*>(swp + lane * NO + 4 * c);
                xr[4 * c + 0] = v.x;
                xr[4 * c + 1] = v.y;
                xr[4 * c + 2] = v.z;
                xr[4 * c + 3] = v.w;
            }

            // 4 outputs x 9 packed-tap FFMA2; both lanes accumulate the SAME output
            uint64_t acc[NO];
#pragma unroll
            for (int oo = 0; oo < NO; ++oo) {
                acc[oo] = bp[oo];
                const int ms = oo >> 1;
#pragma unroll
                for (int m = 0; m < NP; ++m) {
                    const int am = ms + m;
                    fma2f(acc[oo], xr[2 * am], xr[2 * am + 1], wpk[oo][m]);
                }
            }

            float4 o4;
            {
                float lo, hi;
                upk2(lo, hi, acc[0]); o4.x = lo + hi;
                upk2(lo, hi, acc[1]); o4.y = lo + hi;
                upk2(lo, hi, acc[2]); o4.z = lo + hi;
                upk2(lo, hi, acc[3]); o4.w = lo + hi;
            }
            *reinterpret_cast<float4*>(out + (long)nt * OUT_F + o_base) = o4;
        }

        buf  = (buf  + 2) & (NBUF - 1);
        pbuf = (pbuf + 2) & (NBUF - 1);
    }
}

extern "C" void kernel_launch(void* const* d_in, const int* in_sizes, int n_in,
                              void* d_out, int out_size)
{
    const float* x    = (const float*)d_in[0];   // [NTOK, IN_F]
    const float* w    = (const float*)d_in[1];   // [OUT_F, IN_F]
    const float* bias = (const float*)d_in[2];   // [OUT_F]
    float* out = (float*)d_out;

    cudaFuncSetAttribute(band_linear_kernel,
                         cudaFuncAttributeMaxDynamicSharedMemorySize, SMEM_B);

    dim3 grid(OUT_F / (WARPS * 32 * NO), GY);    // (4, 256)
    dim3 block(WARPS * 32);                      // 256
    band_linear_kernel<<<grid, block, SMEM_B>>>(x, w, bias, out);
}